// round 10
// baseline (speedup 1.0000x reference)
#include <cuda_runtime.h>

// MLP_89498528514757 — fused recommender MLP, fp32. Round 10:
// R5 shape (grid 256 x 512, 2 blocks/SM, ROWS=4) but split-K folded INSIDE
// each warp: layer 2 = 8 j-cols x 4 k-slices per warp, layer 3 = 4 j-cols x
// 8 k-slices; partials reduced with shfl_xor butterflies instead of
// smem + __syncthreads. Block barriers: 5 -> 3.

#define NUM_USERS 100000
#define BATCH     1024
#define ROWS      4

__global__ __launch_bounds__(512, 2)
void mlp_fused_kernel(const int*   __restrict__ user_ids,
                      const int*   __restrict__ item_ids,
                      const float* __restrict__ W1, const float* __restrict__ b1,
                      const float* __restrict__ W2, const float* __restrict__ b2,
                      const float* __restrict__ W3, const float* __restrict__ b3,
                      const float* __restrict__ W4, const float* __restrict__ b4,
                      float*       __restrict__ out)
{
    __shared__ float4 h1t[256];                 // [k] -> 4 rows   (4 KB)
    __shared__ float4 h2t[128];                 // [k] -> 4 rows   (2 KB)
    __shared__ float4 h3t[64];                  // [j] -> 4 rows   (1 KB)

    const int t    = threadIdx.x;               // 0..511
    const int w    = t >> 5;                    // warp 0..15
    const int l    = t & 31;                    // lane
    const int row0 = blockIdx.x * ROWS;

    // ---------------- Layer 1: dependent DRAM gather chain FIRST -----------
    const int k1 = t & 255;
    const int g  = t >> 8;                      // 0/1 -> rows {2g, 2g+1}
    const int ra = row0 + g * 2;
    const int ua = user_ids[ra],     ia = item_ids[ra];
    const int ub = user_ids[ra + 1], ib = item_ids[ra + 1];
    const float ga = W1[ua * 256 + k1], ea = W1[(NUM_USERS + ia) * 256 + k1];
    const float gb = W1[ub * 256 + k1], eb = W1[(NUM_USERS + ib) * 256 + k1];

    // ---- overlap while the gather is in flight ----------------------------
    // layer 2 mapping: j = w*8 + (l&7), k-slice ks2 = l>>3 (4-way, 64 iters)
    const int j2  = w * 8 + (l & 7);
    const int ks2 = l >> 3;
    const float* __restrict__ w2p = W2 + (ks2 * 64) * 128 + j2;
    float w2pre[16];
    #pragma unroll
    for (int i = 0; i < 16; ++i) w2pre[i] = w2p[i * 128];

    const float bj2 = b2[j2];
    // layer 3 mapping: j = w*4 + (l&3), k-slice ks3 = l>>2 (8-way, 16 iters)
    const int j3  = w * 4 + (l & 3);
    const int ks3 = l >> 2;
    const float bj3 = b3[j3];
    float w4a = 0.f, w4b = 0.f, bb4 = 0.f;
    if (t < 32) { w4a = W4[t]; w4b = W4[t + 32]; bb4 = b4[0]; }

    // finish layer 1 (thread writes its 2 rows of h1t[k1])
    {
        const float bk = b1[k1];
        float2 h;
        h.x = fmaxf(ga + ea + bk, 0.f);
        h.y = fmaxf(gb + eb + bk, 0.f);
        *reinterpret_cast<float2*>(
            reinterpret_cast<float*>(&h1t[k1]) + g * 2) = h;
    }
    __syncthreads();                            // BAR 1

    // ---------------- Layer 2: [4x256] @ W2[256x128], warp-local 4-way K ---
    float4 a2 = make_float4(0.f, 0.f, 0.f, 0.f);
    {
        #pragma unroll
        for (int kk = 0; kk < 16; ++kk) {       // weights already in regs
            const float  wv = w2pre[kk];
            const float4 v  = h1t[ks2 * 64 + kk];
            a2.x = fmaf(v.x, wv, a2.x);  a2.y = fmaf(v.y, wv, a2.y);
            a2.z = fmaf(v.z, wv, a2.z);  a2.w = fmaf(v.w, wv, a2.w);
        }
        #pragma unroll
        for (int kk = 16; kk < 64; ++kk) {
            const float  wv = w2p[kk * 128];    // LDG (L2-resident)
            const float4 v  = h1t[ks2 * 64 + kk];
            a2.x = fmaf(v.x, wv, a2.x);  a2.y = fmaf(v.y, wv, a2.y);
            a2.z = fmaf(v.z, wv, a2.z);  a2.w = fmaf(v.w, wv, a2.w);
        }
    }
    // layer-3 weights into regs while the shuffle reduce proceeds
    float w3pre[16];
    {
        const float* __restrict__ w3p = W3 + (ks3 * 16) * 64 + j3;
        #pragma unroll
        for (int i = 0; i < 16; ++i) w3pre[i] = w3p[i * 64];
    }
    // butterfly-reduce the 4 k-slices (lanes 8 and 16 apart share j)
    #pragma unroll
    for (int off = 8; off <= 16; off <<= 1) {
        a2.x += __shfl_xor_sync(0xffffffffu, a2.x, off);
        a2.y += __shfl_xor_sync(0xffffffffu, a2.y, off);
        a2.z += __shfl_xor_sync(0xffffffffu, a2.z, off);
        a2.w += __shfl_xor_sync(0xffffffffu, a2.w, off);
    }
    if (l < 8) {                                // lanes 0-7 own final j
        h2t[j2] = make_float4(fmaxf(a2.x + bj2, 0.f), fmaxf(a2.y + bj2, 0.f),
                              fmaxf(a2.z + bj2, 0.f), fmaxf(a2.w + bj2, 0.f));
    }
    __syncthreads();                            // BAR 2

    // ---------------- Layer 3: [4x128] @ W3[128x64], warp-local 8-way K ----
    float4 a3 = make_float4(0.f, 0.f, 0.f, 0.f);
    {
        #pragma unroll
        for (int kk = 0; kk < 16; ++kk) {
            const float  wv = w3pre[kk];
            const float4 v  = h2t[ks3 * 16 + kk];
            a3.x = fmaf(v.x, wv, a3.x);  a3.y = fmaf(v.y, wv, a3.y);
            a3.z = fmaf(v.z, wv, a3.z);  a3.w = fmaf(v.w, wv, a3.w);
        }
    }
    #pragma unroll
    for (int off = 4; off <= 16; off <<= 1) {   // reduce 8 slices (4,8,16)
        a3.x += __shfl_xor_sync(0xffffffffu, a3.x, off);
        a3.y += __shfl_xor_sync(0xffffffffu, a3.y, off);
        a3.z += __shfl_xor_sync(0xffffffffu, a3.z, off);
        a3.w += __shfl_xor_sync(0xffffffffu, a3.w, off);
    }
    if (l < 4) {
        h3t[j3] = make_float4(fmaxf(a3.x + bj3, 0.f), fmaxf(a3.y + bj3, 0.f),
                              fmaxf(a3.z + bj3, 0.f), fmaxf(a3.w + bj3, 0.f));
    }
    __syncthreads();                            // BAR 3

    // ---------------- Layer 4: [4x64] @ W4[64x1] + b4 (warp 0) -------------
    if (t < 32) {
        const float4 va = h3t[t], vb = h3t[t + 32];
        float a0 = fmaf(va.x, w4a, vb.x * w4b);
        float a1 = fmaf(va.y, w4a, vb.y * w4b);
        float a2r = fmaf(va.z, w4a, vb.z * w4b);
        float a3r = fmaf(va.w, w4a, vb.w * w4b);
        #pragma unroll
        for (int off = 16; off > 0; off >>= 1) {
            a0  += __shfl_down_sync(0xffffffffu, a0,  off);
            a1  += __shfl_down_sync(0xffffffffu, a1,  off);
            a2r += __shfl_down_sync(0xffffffffu, a2r, off);
            a3r += __shfl_down_sync(0xffffffffu, a3r, off);
        }
        if (t == 0) {
            out[row0 + 0] = a0  + bb4;
            out[row0 + 1] = a1  + bb4;
            out[row0 + 2] = a2r + bb4;
            out[row0 + 3] = a3r + bb4;
        }
    }
}

extern "C" void kernel_launch(void* const* d_in, const int* in_sizes, int n_in,
                              void* d_out, int out_size)
{
    const int*   user_ids = (const int*)  d_in[0];
    const int*   item_ids = (const int*)  d_in[1];
    const float* W1       = (const float*)d_in[2];
    const float* b1       = (const float*)d_in[3];
    const float* W2       = (const float*)d_in[4];
    const float* b2       = (const float*)d_in[5];
    const float* W3       = (const float*)d_in[6];
    const float* b3       = (const float*)d_in[7];
    const float* W4       = (const float*)d_in[8];
    const float* b4       = (const float*)d_in[9];
    float*       out      = (float*)d_out;

    mlp_fused_kernel<<<BATCH / ROWS, 512>>>(user_ids, item_ids,
                                            W1, b1, W2, b2, W3, b3, W4, b4, out);
}

// round 11
// speedup vs baseline: 1.5471x; 1.5471x over previous
#include <cuda_runtime.h>

// MLP_89498528514757 — fused recommender MLP, fp32. Round 11:
// R5 (best: ncu 9.4us) with exact 2-blocks-per-SM tiling: grid 296 = 2*148.
// Blocks 0..159 process 3 rows, blocks 160..295 process 4 rows (3*160+4*136
// = 1024). 3-row blocks clamp the 4th row slot to a duplicate row (compute
// only) and guard the store. Everything else identical to R5: 512 threads,
// __launch_bounds__(512,2), 4-way L2 / 8-way L3 split-K, reg-prefetched
// weight heads, cross-barrier W3 prefetch.

#define NUM_USERS 100000
#define BATCH     1024

__global__ __launch_bounds__(512, 2)
void mlp_fused_kernel(const int*   __restrict__ user_ids,
                      const int*   __restrict__ item_ids,
                      const float* __restrict__ W1, const float* __restrict__ b1,
                      const float* __restrict__ W2, const float* __restrict__ b2,
                      const float* __restrict__ W3, const float* __restrict__ b3,
                      const float* __restrict__ W4, const float* __restrict__ b4,
                      float*       __restrict__ out)
{
    __shared__ float4 h1t[256];      // h1[k], 4 row slots   (4 KB)
    __shared__ float4 h2p[512];      // layer-2 partials      (8 KB)
    __shared__ float4 h2t[128];      // h2[k], 4 row slots    (2 KB)
    __shared__ float4 h3p[512];      // layer-3 partials      (8 KB)
    __shared__ float4 h3t[64];       // h3[j], 4 row slots    (1 KB)

    const int t = threadIdx.x;       // 0..511
    const int b = blockIdx.x;        // 0..295

    // variable-rows mapping: 160 blocks x 3 rows + 136 blocks x 4 rows
    int row0, nr;
    if (b < 160) { row0 = b * 3;              nr = 3; }
    else         { row0 = 480 + (b - 160) * 4; nr = 4; }

    // ---------------- Layer 1: start the dependent DRAM chain FIRST --------
    // Thread t: feature k = t&255, pair g = t>>8 owns row slots {2g, 2g+1}
    // (slot indices clamped to nr-1 for 3-row blocks; slot 3 duplicates 2).
    const int k1 = t & 255;
    const int g  = t >> 8;                        // 0 or 1
    const int sa = g * 2;
    const int sb = g * 2 + 1;
    const int ra  = row0 + (sa < nr ? sa : nr - 1);
    const int rbw = row0 + (sb < nr ? sb : nr - 1);
    const int ua = user_ids[ra],  ia = item_ids[ra];
    const int ub = user_ids[rbw], ib = item_ids[rbw];
    const float ga = W1[ua * 256 + k1], ea = W1[(NUM_USERS + ia) * 256 + k1];
    const float gb = W1[ub * 256 + k1], eb = W1[(NUM_USERS + ib) * 256 + k1];

    // ---- overlap: biases + layer-2 weight prefetch while gather in flight --
    const int j2  = t & 127;
    const int kq2 = t >> 7;                       // 0..3 (k-quarter, 64 iters)
    const float* __restrict__ w2p = W2 + (kq2 * 64) * 128 + j2;
    float w2pre[16];
    #pragma unroll
    for (int i = 0; i < 16; ++i) w2pre[i] = w2p[i * 128];

    const float bj2 = b2[j2];
    const float bj3 = b3[t & 63];
    float w4a = 0.f, w4b = 0.f, bb4 = 0.f;
    if (t < 32) { w4a = W4[t]; w4b = W4[t + 32]; bb4 = b4[0]; }

    // finish layer 1: each thread writes its 2 row slots (8B STS)
    {
        const float bk = b1[k1];
        float2 h;
        h.x = fmaxf(ga + ea + bk, 0.f);
        h.y = fmaxf(gb + eb + bk, 0.f);
        *reinterpret_cast<float2*>(
            reinterpret_cast<float*>(&h1t[k1]) + g * 2) = h;
    }
    __syncthreads();

    // ---------------- Layer 2: [4 x 256] @ W2[256 x 128], 4-way split-K ----
    {
        float4 a = make_float4(0.f, 0.f, 0.f, 0.f);
        #pragma unroll
        for (int kk = 0; kk < 16; ++kk) {         // prefetched weights
            const float  w = w2pre[kk];
            const float4 v = h1t[kq2 * 64 + kk];
            a.x = fmaf(v.x, w, a.x);  a.y = fmaf(v.y, w, a.y);
            a.z = fmaf(v.z, w, a.z);  a.w = fmaf(v.w, w, a.w);
        }
        #pragma unroll
        for (int kk = 16; kk < 64; ++kk) {
            const float  w = w2p[kk * 128];
            const float4 v = h1t[kq2 * 64 + kk];
            a.x = fmaf(v.x, w, a.x);  a.y = fmaf(v.y, w, a.y);
            a.z = fmaf(v.z, w, a.z);  a.w = fmaf(v.w, w, a.w);
        }
        h2p[t] = a;
    }

    // ---- layer-3 weight prefetch (all 16 iters) before the sync ----
    const int j3  = t & 63;
    const int k83 = t >> 6;                       // 0..7 (16 iters)
    float w3pre[16];
    {
        const float* __restrict__ w3p = W3 + (k83 * 16) * 64 + j3;
        #pragma unroll
        for (int i = 0; i < 16; ++i) w3pre[i] = w3p[i * 64];
    }
    __syncthreads();

    // combine 4 layer-2 partials, +b2, ReLU
    if (t < 128) {
        const float4 p0 = h2p[t],       p1 = h2p[t + 128];
        const float4 p2 = h2p[t + 256], p3 = h2p[t + 384];
        h2t[t] = make_float4(
            fmaxf(p0.x + p1.x + p2.x + p3.x + bj2, 0.f),
            fmaxf(p0.y + p1.y + p2.y + p3.y + bj2, 0.f),
            fmaxf(p0.z + p1.z + p2.z + p3.z + bj2, 0.f),
            fmaxf(p0.w + p1.w + p2.w + p3.w + bj2, 0.f));
    }
    __syncthreads();

    // ---------------- Layer 3: [4 x 128] @ W3[128 x 64], 8-way split-K -----
    {
        float4 a = make_float4(0.f, 0.f, 0.f, 0.f);
        #pragma unroll
        for (int kk = 0; kk < 16; ++kk) {
            const float  w = w3pre[kk];
            const float4 v = h2t[k83 * 16 + kk];
            a.x = fmaf(v.x, w, a.x);  a.y = fmaf(v.y, w, a.y);
            a.z = fmaf(v.z, w, a.z);  a.w = fmaf(v.w, w, a.w);
        }
        h3p[t] = a;
    }
    __syncthreads();

    // combine 8 layer-3 partials, +b3, ReLU
    if (t < 64) {
        float4 s = make_float4(bj3, bj3, bj3, bj3);
        #pragma unroll
        for (int p = 0; p < 8; ++p) {
            const float4 v = h3p[t + 64 * p];
            s.x += v.x; s.y += v.y; s.z += v.z; s.w += v.w;
        }
        h3t[t] = make_float4(fmaxf(s.x, 0.f), fmaxf(s.y, 0.f),
                             fmaxf(s.z, 0.f), fmaxf(s.w, 0.f));
    }
    __syncthreads();

    // ---------------- Layer 4: [nr x 64] @ W4[64 x 1] + b4 (warp 0) --------
    if (t < 32) {
        const float4 va = h3t[t], vb = h3t[t + 32];
        float a0 = fmaf(va.x, w4a, vb.x * w4b);
        float a1 = fmaf(va.y, w4a, vb.y * w4b);
        float a2 = fmaf(va.z, w4a, vb.z * w4b);
        float a3 = fmaf(va.w, w4a, vb.w * w4b);
        #pragma unroll
        for (int off = 16; off > 0; off >>= 1) {
            a0 += __shfl_down_sync(0xffffffffu, a0, off);
            a1 += __shfl_down_sync(0xffffffffu, a1, off);
            a2 += __shfl_down_sync(0xffffffffu, a2, off);
            a3 += __shfl_down_sync(0xffffffffu, a3, off);
        }
        if (t == 0) {
            out[row0 + 0] = a0 + bb4;
            out[row0 + 1] = a1 + bb4;
            out[row0 + 2] = a2 + bb4;
            if (nr == 4) out[row0 + 3] = a3 + bb4;
        }
    }
}

extern "C" void kernel_launch(void* const* d_in, const int* in_sizes, int n_in,
                              void* d_out, int out_size)
{
    const int*   user_ids = (const int*)  d_in[0];
    const int*   item_ids = (const int*)  d_in[1];
    const float* W1       = (const float*)d_in[2];
    const float* b1       = (const float*)d_in[3];
    const float* W2       = (const float*)d_in[4];
    const float* b2       = (const float*)d_in[5];
    const float* W3       = (const float*)d_in[6];
    const float* b3       = (const float*)d_in[7];
    const float* W4       = (const float*)d_in[8];
    const float* b4       = (const float*)d_in[9];
    float*       out      = (float*)d_out;

    mlp_fused_kernel<<<296, 512>>>(user_ids, item_ids,
                                   W1, b1, W2, b2, W3, b3, W4, b4, out);
}

// round 12
// speedup vs baseline: 1.7589x; 1.1369x over previous
#include <cuda_runtime.h>

// MLP_89498528514757 — fused recommender MLP, fp32. Round 12:
// R5 skeleton (grid 256 x 512, 2 blocks/SM, ROWS=4) with layer-2 split-K
// deepened 4 -> 8 while preserving warp coalescing: 64 j-pairs x 8 k-slices,
// each thread owns 2 consecutive j columns (float2 weight LDG.64, lanes span
// 256B contiguous). Serial k-loop halves: 64 -> 32 iters (24 post-prefetch
// LDGs), 8 independent FFMA chains/thread. Combine2 = 8-deep over all 512
// threads, conflict-free. Layer 3/4 identical to R5 (best measured).

#define NUM_USERS 100000
#define BATCH     1024
#define ROWS      4

__global__ __launch_bounds__(512, 2)
void mlp_fused_kernel(const int*   __restrict__ user_ids,
                      const int*   __restrict__ item_ids,
                      const float* __restrict__ W1, const float* __restrict__ b1,
                      const float* __restrict__ W2, const float* __restrict__ b2,
                      const float* __restrict__ W3, const float* __restrict__ b3,
                      const float* __restrict__ W4, const float* __restrict__ b4,
                      float*       __restrict__ out)
{
    __shared__ float4 h1t[256];                 // [k] -> 4 rows       (4 KB)
    __shared__ union {
        float4 l2[8][128];                      // [ks][j] -> 4 rows  (16 KB)
        float4 l3[8][64];                       // [ks][j] -> 4 rows   (8 KB)
    } P;
    __shared__ float4 h2t[128];                 // [k] -> 4 rows       (2 KB)
    __shared__ float4 h3t[64];                  // [j] -> 4 rows       (1 KB)

    const int t    = threadIdx.x;               // 0..511
    const int row0 = blockIdx.x * ROWS;

    // ---------------- Layer 1: start the dependent DRAM chain FIRST --------
    const int k1 = t & 255;
    const int g  = t >> 8;                      // 0/1 -> rows {2g, 2g+1}
    const int ra = row0 + g * 2;
    const int ua = user_ids[ra],     ia = item_ids[ra];
    const int ub = user_ids[ra + 1], ib = item_ids[ra + 1];
    const float ga = W1[ua * 256 + k1], ea = W1[(NUM_USERS + ia) * 256 + k1];
    const float gb = W1[ub * 256 + k1], eb = W1[(NUM_USERS + ib) * 256 + k1];

    // ---- overlap while the gather is in flight ----------------------------
    // layer 2: j-pair jp = t&63 -> cols {2jp, 2jp+1}; k-slice ks = t>>6 (0..7)
    const int jp = t & 63;
    const int ks = t >> 6;
    const float2* __restrict__ w2p =
        reinterpret_cast<const float2*>(W2) + (ks * 32) * 64 + jp;
    float2 w2pre[8];
    #pragma unroll
    for (int i = 0; i < 8; ++i) w2pre[i] = w2p[i * 64];   // head: 8 of 32 iters

    // layer 3: j3 = t&63, k-slice k83 = t>>6 (8-way, 16 iters, all in regs)
    const int j3  = t & 63;
    const int k83 = t >> 6;
    float w3pre[16];
    {
        const float* __restrict__ w3p = W3 + (k83 * 16) * 64 + j3;
        #pragma unroll
        for (int i = 0; i < 16; ++i) w3pre[i] = w3p[i * 64];
    }

    const float bj2 = b2[t >> 2];               // combine2: j = t>>2
    const float bj3 = b3[t & 63];
    float w4a = 0.f, w4b = 0.f, bb4 = 0.f;
    if (t < 32) { w4a = W4[t]; w4b = W4[t + 32]; bb4 = b4[0]; }

    // finish layer 1: thread writes its 2 rows of h1t[k1] (8B STS)
    {
        const float bk = b1[k1];
        float2 h;
        h.x = fmaxf(ga + ea + bk, 0.f);
        h.y = fmaxf(gb + eb + bk, 0.f);
        *reinterpret_cast<float2*>(
            reinterpret_cast<float*>(&h1t[k1]) + g * 2) = h;
    }
    __syncthreads();

    // ---------------- Layer 2: [4x256] @ W2[256x128], 8-way K, 2 j/thread --
    {
        float4 ae = make_float4(0.f, 0.f, 0.f, 0.f);   // col 2jp,   rows 0-3
        float4 ao = make_float4(0.f, 0.f, 0.f, 0.f);   // col 2jp+1, rows 0-3
        #pragma unroll
        for (int kk = 0; kk < 8; ++kk) {        // weights already in regs
            const float2 w = w2pre[kk];
            const float4 v = h1t[ks * 32 + kk]; // broadcast LDS.128
            ae.x = fmaf(v.x, w.x, ae.x);  ae.y = fmaf(v.y, w.x, ae.y);
            ae.z = fmaf(v.z, w.x, ae.z);  ae.w = fmaf(v.w, w.x, ae.w);
            ao.x = fmaf(v.x, w.y, ao.x);  ao.y = fmaf(v.y, w.y, ao.y);
            ao.z = fmaf(v.z, w.y, ao.z);  ao.w = fmaf(v.w, w.y, ao.w);
        }
        #pragma unroll
        for (int kk = 8; kk < 32; ++kk) {
            const float2 w = w2p[kk * 64];      // LDG.64, warp spans 256B
            const float4 v = h1t[ks * 32 + kk];
            ae.x = fmaf(v.x, w.x, ae.x);  ae.y = fmaf(v.y, w.x, ae.y);
            ae.z = fmaf(v.z, w.x, ae.z);  ae.w = fmaf(v.w, w.x, ae.w);
            ao.x = fmaf(v.x, w.y, ao.x);  ao.y = fmaf(v.y, w.y, ao.y);
            ao.z = fmaf(v.z, w.y, ao.z);  ao.w = fmaf(v.w, w.y, ao.w);
        }
        P.l2[ks][jp * 2 + 0] = ae;              // STS.128, j-contiguous
        P.l2[ks][jp * 2 + 1] = ao;
    }
    __syncthreads();

    // combine layer-2 partials: all 512 threads, element (j = t>>2, r = t&3)
    {
        const int j = t >> 2, r = t & 3;
        float s = bj2;
        #pragma unroll
        for (int q = 0; q < 8; ++q)             // LDS.32, lanes hit words 0..31
            s += reinterpret_cast<const float*>(&P.l2[q][j])[r];
        reinterpret_cast<float*>(&h2t[j])[r] = fmaxf(s, 0.f);
    }
    __syncthreads();

    // ---------------- Layer 3: [4x128] @ W3[128x64], 8-way split-K ---------
    {
        float4 a = make_float4(0.f, 0.f, 0.f, 0.f);
        #pragma unroll
        for (int kk = 0; kk < 16; ++kk) {
            const float  w = w3pre[kk];
            const float4 v = h2t[k83 * 16 + kk];
            a.x = fmaf(v.x, w, a.x);  a.y = fmaf(v.y, w, a.y);
            a.z = fmaf(v.z, w, a.z);  a.w = fmaf(v.w, w, a.w);
        }
        P.l3[k83][j3] = a;
    }
    __syncthreads();

    // combine layer-3 partials: 256 threads, element (j = t>>2, r = t&3)
    if (t < 256) {
        const int j = t >> 2, r = t & 3;
        float s = bj3;
        // bj3 above was loaded per t&63; recompute the right bias for j:
        s = b3[j];
        #pragma unroll
        for (int q = 0; q < 8; ++q)
            s += reinterpret_cast<const float*>(&P.l3[q][j])[r];
        reinterpret_cast<float*>(&h3t[j])[r] = fmaxf(s, 0.f);
    }
    __syncthreads();

    // ---------------- Layer 4: [4x64] @ W4[64x1] + b4 (warp 0) -------------
    if (t < 32) {
        const float4 va = h3t[t], vb = h3t[t + 32];
        float a0 = fmaf(va.x, w4a, vb.x * w4b);
        float a1 = fmaf(va.y, w4a, vb.y * w4b);
        float a2 = fmaf(va.z, w4a, vb.z * w4b);
        float a3 = fmaf(va.w, w4a, vb.w * w4b);
        #pragma unroll
        for (int off = 16; off > 0; off >>= 1) {
            a0 += __shfl_down_sync(0xffffffffu, a0, off);
            a1 += __shfl_down_sync(0xffffffffu, a1, off);
            a2 += __shfl_down_sync(0xffffffffu, a2, off);
            a3 += __shfl_down_sync(0xffffffffu, a3, off);
        }
        if (t == 0) {
            out[row0 + 0] = a0 + bb4;
            out[row0 + 1] = a1 + bb4;
            out[row0 + 2] = a2 + bb4;
            out[row0 + 3] = a3 + bb4;
        }
    }
}

extern "C" void kernel_launch(void* const* d_in, const int* in_sizes, int n_in,
                              void* d_out, int out_size)
{
    const int*   user_ids = (const int*)  d_in[0];
    const int*   item_ids = (const int*)  d_in[1];
    const float* W1       = (const float*)d_in[2];
    const float* b1       = (const float*)d_in[3];
    const float* W2       = (const float*)d_in[4];
    const float* b2       = (const float*)d_in[5];
    const float* W3       = (const float*)d_in[6];
    const float* b3       = (const float*)d_in[7];
    const float* W4       = (const float*)d_in[8];
    const float* b4       = (const float*)d_in[9];
    float*       out      = (float*)d_out;

    mlp_fused_kernel<<<BATCH / ROWS, 512>>>(user_ids, item_ids,
                                            W1, b1, W2, b2, W3, b3, W4, b4, out);
}

// round 14
// speedup vs baseline: 1.7642x; 1.0030x over previous
#include <cuda_runtime.h>

// MLP_89498528514757 — fused recommender MLP, fp32. Round 13:
// R12 structure (grid 256 x 512, 2 blocks/SM, ROWS=4, 8-way L2 / 8-way L3
// split-K, j-pair coalesced weights) with the row dimension packed into
// Blackwell f32x2 registers: fma.rn.f32x2 (SASS FFMA2) does 2 row-MACs per
// instruction. Layer-2 iter: LDS.128 + LDG.64 + 2 packs + 4 FFMA2 (was 8
// FFMA). Full fp32 precision — rel_err unchanged.

#define NUM_USERS 100000
#define BATCH     1024
#define ROWS      4

typedef unsigned long long u64;

__device__ __forceinline__ u64 fma2(u64 a, u64 b, u64 c) {
    u64 d;
    asm("fma.rn.f32x2 %0, %1, %2, %3;" : "=l"(d) : "l"(a), "l"(b), "l"(c));
    return d;
}
__device__ __forceinline__ u64 pack2(float x) {
    u64 d;
    asm("mov.b64 %0, {%1, %1};" : "=l"(d) : "f"(x));
    return d;
}

__global__ __launch_bounds__(512, 2)
void mlp_fused_kernel(const int*   __restrict__ user_ids,
                      const int*   __restrict__ item_ids,
                      const float* __restrict__ W1, const float* __restrict__ b1,
                      const float* __restrict__ W2, const float* __restrict__ b2,
                      const float* __restrict__ W3, const float* __restrict__ b3,
                      const float* __restrict__ W4, const float* __restrict__ b4,
                      float*       __restrict__ out)
{
    __shared__ float4 h1t[256];                 // [k] -> rows 01|23   (4 KB)
    __shared__ union {
        float4 l2[8][128];                      // [ks][j] -> 4 rows  (16 KB)
        float4 l3[8][64];                       // [ks][j] -> 4 rows   (8 KB)
    } P;
    __shared__ float4 h2t[128];                 // [k] -> 4 rows       (2 KB)
    __shared__ float4 h3t[64];                  // [j] -> 4 rows       (1 KB)

    const int t    = threadIdx.x;               // 0..511
    const int row0 = blockIdx.x * ROWS;

    // ---------------- Layer 1: start the dependent DRAM chain FIRST --------
    const int k1 = t & 255;
    const int g  = t >> 8;                      // 0/1 -> rows {2g, 2g+1}
    const int ra = row0 + g * 2;
    const int ua = user_ids[ra],     ia = item_ids[ra];
    const int ub = user_ids[ra + 1], ib = item_ids[ra + 1];
    const float ga = W1[ua * 256 + k1], ea = W1[(NUM_USERS + ia) * 256 + k1];
    const float gb = W1[ub * 256 + k1], eb = W1[(NUM_USERS + ib) * 256 + k1];

    // ---- overlap while the gather is in flight ----------------------------
    // layer 2: j-pair jp = t&63 -> cols {2jp, 2jp+1}; k-slice ks = t>>6 (0..7)
    const int jp = t & 63;
    const int ks = t >> 6;
    const float2* __restrict__ w2p =
        reinterpret_cast<const float2*>(W2) + (ks * 32) * 64 + jp;
    float2 w2pre[8];
    #pragma unroll
    for (int i = 0; i < 8; ++i) w2pre[i] = w2p[i * 64];   // head: 8 of 32 iters

    // layer 3: j3 = t&63, k-slice k83 = t>>6 (8-way, 16 iters, all in regs)
    const int j3  = t & 63;
    const int k83 = t >> 6;
    float w3pre[16];
    {
        const float* __restrict__ w3p = W3 + (k83 * 16) * 64 + j3;
        #pragma unroll
        for (int i = 0; i < 16; ++i) w3pre[i] = w3p[i * 64];
    }

    const float bj2 = b2[t >> 2];               // combine2: j = t>>2
    float w4a = 0.f, w4b = 0.f, bb4 = 0.f;
    if (t < 32) { w4a = W4[t]; w4b = W4[t + 32]; bb4 = b4[0]; }

    // finish layer 1: thread writes its 2 rows of h1t[k1] (8B STS)
    {
        const float bk = b1[k1];
        float2 h;
        h.x = fmaxf(ga + ea + bk, 0.f);
        h.y = fmaxf(gb + eb + bk, 0.f);
        *reinterpret_cast<float2*>(
            reinterpret_cast<float*>(&h1t[k1]) + g * 2) = h;
    }
    __syncthreads();

    // ------- Layer 2: [4x256] @ W2[256x128], 8-way K, 2 j/thread, FFMA2 ----
    {
        u64 ae01 = 0ull, ae23 = 0ull;           // col 2jp:   rows 01 | 23
        u64 ao01 = 0ull, ao23 = 0ull;           // col 2jp+1: rows 01 | 23
        #pragma unroll
        for (int kk = 0; kk < 8; ++kk) {        // weights already in regs
            const float2 w = w2pre[kk];
            const ulonglong2 v =
                *reinterpret_cast<const ulonglong2*>(&h1t[ks * 32 + kk]);
            const u64 wx = pack2(w.x), wy = pack2(w.y);
            ae01 = fma2(v.x, wx, ae01);  ae23 = fma2(v.y, wx, ae23);
            ao01 = fma2(v.x, wy, ao01);  ao23 = fma2(v.y, wy, ao23);
        }
        #pragma unroll
        for (int kk = 8; kk < 32; ++kk) {
            const float2 w = w2p[kk * 64];      // LDG.64, warp spans 256B
            const ulonglong2 v =
                *reinterpret_cast<const ulonglong2*>(&h1t[ks * 32 + kk]);
            const u64 wx = pack2(w.x), wy = pack2(w.y);
            ae01 = fma2(v.x, wx, ae01);  ae23 = fma2(v.y, wx, ae23);
            ao01 = fma2(v.x, wy, ao01);  ao23 = fma2(v.y, wy, ao23);
        }
        ulonglong2 se; se.x = ae01; se.y = ae23;
        ulonglong2 so; so.x = ao01; so.y = ao23;
        *reinterpret_cast<ulonglong2*>(&P.l2[ks][jp * 2 + 0]) = se;  // STS.128
        *reinterpret_cast<ulonglong2*>(&P.l2[ks][jp * 2 + 1]) = so;
    }
    __syncthreads();

    // combine layer-2 partials: all 512 threads, element (j = t>>2, r = t&3)
    {
        const int j = t >> 2, r = t & 3;
        float s = bj2;
        #pragma unroll
        for (int q = 0; q < 8; ++q)
            s += reinterpret_cast<const float*>(&P.l2[q][j])[r];
        reinterpret_cast<float*>(&h2t[j])[r] = fmaxf(s, 0.f);
    }
    __syncthreads();

    // ------- Layer 3: [4x128] @ W3[128x64], 8-way split-K, FFMA2 -----------
    {
        u64 a01 = 0ull, a23 = 0ull;
        #pragma unroll
        for (int kk = 0; kk < 16; ++kk) {
            const u64 ww = pack2(w3pre[kk]);
            const ulonglong2 v =
                *reinterpret_cast<const ulonglong2*>(&h2t[k83 * 16 + kk]);
            a01 = fma2(v.x, ww, a01);
            a23 = fma2(v.y, ww, a23);
        }
        ulonglong2 sv; sv.x = a01; sv.y = a23;
        *reinterpret_cast<ulonglong2*>(&P.l3[k83][j3]) = sv;
    }
    __syncthreads();

    // combine layer-3 partials: 256 threads, element (j = t>>2, r = t&3)
    if (t < 256) {
        const int j = t >> 2, r = t & 3;
        float s = b3[j];
        #pragma unroll
        for (int q = 0; q < 8; ++q)
            s += reinterpret_cast<const float*>(&P.l3[q][j])[r];
        reinterpret_cast<float*>(&h3t[j])[r] = fmaxf(s, 0.f);
    }
    __syncthreads();

    // ---------------- Layer 4: [4x64] @ W4[64x1] + b4 (warp 0) -------------
    if (t < 32) {
        const float4 va = h3t[t], vb = h3t[t + 32];
        float a0 = fmaf(va.x, w4a, vb.x * w4b);
        float a1 = fmaf(va.y, w4a, vb.y * w4b);
        float a2 = fmaf(va.z, w4a, vb.z * w4b);
        float a3 = fmaf(va.w, w4a, vb.w * w4b);
        #pragma unroll
        for (int off = 16; off > 0; off >>= 1) {
            a0 += __shfl_down_sync(0xffffffffu, a0, off);
            a1 += __shfl_down_sync(0xffffffffu, a1, off);
            a2 += __shfl_down_sync(0xffffffffu, a2, off);
            a3 += __shfl_down_sync(0xffffffffu, a3, off);
        }
        if (t == 0) {
            out[row0 + 0] = a0 + bb4;
            out[row0 + 1] = a1 + bb4;
            out[row0 + 2] = a2 + bb4;
            out[row0 + 3] = a3 + bb4;
        }
    }
}

extern "C" void kernel_launch(void* const* d_in, const int* in_sizes, int n_in,
                              void* d_out, int out_size)
{
    const int*   user_ids = (const int*)  d_in[0];
    const int*   item_ids = (const int*)  d_in[1];
    const float* W1       = (const float*)d_in[2];
    const float* b1       = (const float*)d_in[3];
    const float* W2       = (const float*)d_in[4];
    const float* b2       = (const float*)d_in[5];
    const float* W3       = (const float*)d_in[6];
    const float* b3       = (const float*)d_in[7];
    const float* W4       = (const float*)d_in[8];
    const float* b4       = (const float*)d_in[9];
    float*       out      = (float*)d_out;

    mlp_fused_kernel<<<BATCH / ROWS, 512>>>(user_ids, item_ids,
                                            W1, b1, W2, b2, W3, b3, W4, b4, out);
}